// round 7
// baseline (speedup 1.0000x reference)
#include <cuda_runtime.h>
#include <cuda_bf16.h>
#include <cstdint>

// SpMM (COO, rows sorted): out[r,:] = sum_{e: rows[e]==r} vals[e] * embeds[cols[e],:]
// N=50000, E=800000, D=64, fp32. rows/cols int32.
//
// R6: half-warp-per-row + float4.
//  - lanes 0-15 handle row 2w, lanes 16-31 handle row 2w+1
//  - gather: 16 lanes x float4 = 256B row -> one LDG.128 inst covers 2 edges
//  - metadata: per-half broadcast LDG.64 of packed (col,val) -> 1 inst / 2 edges
//  - two independent gather chains per warp (2x MLP at same occupancy)
//  - store: rows 2w,2w+1 contiguous -> one coalesced 512B warp store

#define D_FEAT    64
#define MAX_NODES 65537
#define MAX_EDGES (1 << 20)

__device__ int    g_row_ptr[MAX_NODES + 1];
__device__ float2 g_edges[MAX_EDGES];          // (.x = bitcast col, .y = val)

__global__ void build_pack(const int*   __restrict__ rows,
                           const int*   __restrict__ cols,
                           const float* __restrict__ vals,
                           int n_edges, int n_nodes)
{
    int e = blockIdx.x * blockDim.x + threadIdx.x;
    int stride = gridDim.x * blockDim.x;
    for (; e < n_edges; e += stride) {
        g_edges[e] = make_float2(__int_as_float(cols[e]), vals[e]);

        const int r    = rows[e];
        const int prev = (e == 0) ? -1 : rows[e - 1];
        for (int q = prev + 1; q <= r; q++) g_row_ptr[q] = e;     // N+1 total
        if (e == n_edges - 1)
            for (int q = r + 1; q <= n_nodes; q++) g_row_ptr[q] = n_edges;
    }
}

__global__ __launch_bounds__(256)
void spmm_csr(const float* __restrict__ embeds,
              float*       __restrict__ out,
              int n_nodes)
{
    const int warp = (blockIdx.x * blockDim.x + threadIdx.x) >> 5;
    const int lane = threadIdx.x & 31;

    const int half = lane >> 4;            // 0 or 1
    const int fl   = lane & 15;            // float4 slice within the row

    const int row = 2 * warp + half;
    if (row >= n_nodes) return;

    const int start = g_row_ptr[row];
    const int end   = g_row_ptr[row + 1];

    const float4* __restrict__ emb4 = (const float4*)embeds;
    float4 acc = make_float4(0.f, 0.f, 0.f, 0.f);

    // Divergent per-half trip counts; SIMT predication merges the two streams,
    // giving the warp two independent gather chains in flight.
    #pragma unroll 4
    for (int e = start; e < end; e++) {
        const float2 cv = g_edges[e];                // broadcast within half
        const int    c  = __float_as_int(cv.x);
        const float4 t  = emb4[c * (D_FEAT / 4) + fl];
        acc.x = fmaf(cv.y, t.x, acc.x);
        acc.y = fmaf(cv.y, t.y, acc.y);
        acc.z = fmaf(cv.y, t.z, acc.z);
        acc.w = fmaf(cv.y, t.w, acc.w);
    }

    // rows 2w and 2w+1 are adjacent -> warp store is 512B contiguous.
    // Covers every row (empty rows store zeros) -> no memset needed.
    ((float4*)out)[row * (D_FEAT / 4) + fl] = acc;
}

extern "C" void kernel_launch(void* const* d_in, const int* in_sizes, int n_in,
                              void* d_out, int out_size)
{
    const int*   rows   = (const int*)d_in[0];
    const int*   cols   = (const int*)d_in[1];
    const float* vals   = (const float*)d_in[2];
    const float* embeds = (const float*)d_in[3];
    float*       out    = (float*)d_out;

    const int n_edges = in_sizes[0];
    const int n_nodes = out_size / D_FEAT;

    build_pack<<<592, 256>>>(rows, cols, vals, n_edges, n_nodes);

    const int warps  = (n_nodes + 1) / 2;            // half-warp per row
    const int blocks = (warps * 32 + 255) / 256;
    spmm_csr<<<blocks, 256>>>(embeds, out, n_nodes);
}

// round 9
// speedup vs baseline: 1.0490x; 1.0490x over previous
#include <cuda_runtime.h>
#include <cuda_bf16.h>
#include <cstdint>

// SpMM (COO, rows sorted): out[r,:] = sum_{e: rows[e]==r} vals[e] * embeds[cols[e],:]
// N=50000, E=800000, D=64, fp32. rows/cols int32.
//
// R7: (a) drop the packing pass (build only row_ptr, ~1us) — spmm reads
// cols/vals as paired int2/float2 broadcast loads (even-aligned, odd edges
// peeled); (b) pairwise inner loop + unroll 4 -> 8 gathers in flight per
// half-warp (16/warp), halving exposed L2 latency.

#define D_FEAT    64
#define MAX_NODES 65537

__device__ int g_row_ptr[MAX_NODES + 1];

__global__ void build_row_ptr(const int* __restrict__ rows, int n_edges,
                              int n_nodes) {
    int e = blockIdx.x * blockDim.x + threadIdx.x;
    int stride = gridDim.x * blockDim.x;
    for (; e < n_edges; e += stride) {
        const int r    = rows[e];
        const int prev = (e == 0) ? -1 : rows[e - 1];
        for (int q = prev + 1; q <= r; q++) g_row_ptr[q] = e;     // N+1 total
        if (e == n_edges - 1)
            for (int q = r + 1; q <= n_nodes; q++) g_row_ptr[q] = n_edges;
    }
}

__global__ __launch_bounds__(256)
void spmm_csr(const int*   __restrict__ cols,
              const float* __restrict__ vals,
              const float* __restrict__ embeds,
              float*       __restrict__ out,
              int n_nodes)
{
    const int warp = (blockIdx.x * blockDim.x + threadIdx.x) >> 5;
    const int lane = threadIdx.x & 31;

    const int half = lane >> 4;            // lanes 0-15: row 2w, 16-31: row 2w+1
    const int fl   = lane & 15;            // float4 slice within the 64-f row

    const int row = 2 * warp + half;
    if (row >= n_nodes) return;

    const int start = g_row_ptr[row];
    const int end   = g_row_ptr[row + 1];

    const float4* __restrict__ emb4 = (const float4*)embeds;
    float4 acc = make_float4(0.f, 0.f, 0.f, 0.f);

    int e = start;

    // peel leading odd edge so pair loads are 8B-aligned
    if (e < end && (e & 1)) {
        const float v = vals[e];
        const float4 t = emb4[cols[e] * (D_FEAT / 4) + fl];
        acc.x = fmaf(v, t.x, acc.x);
        acc.y = fmaf(v, t.y, acc.y);
        acc.z = fmaf(v, t.z, acc.z);
        acc.w = fmaf(v, t.w, acc.w);
        e++;
    }

    // main pairwise loop: 2 independent gathers per iteration, unroll 4
    // -> 8 gathers in flight per half-warp
    #pragma unroll 4
    for (; e + 1 < end; e += 2) {
        const int2   c2 = *(const int2*)  (cols + e);   // broadcast, L1-hit
        const float2 v2 = *(const float2*)(vals + e);
        const float4 t0 = emb4[c2.x * (D_FEAT / 4) + fl];
        const float4 t1 = emb4[c2.y * (D_FEAT / 4) + fl];
        acc.x = fmaf(v2.x, t0.x, acc.x);
        acc.y = fmaf(v2.x, t0.y, acc.y);
        acc.z = fmaf(v2.x, t0.z, acc.z);
        acc.w = fmaf(v2.x, t0.w, acc.w);
        acc.x = fmaf(v2.y, t1.x, acc.x);
        acc.y = fmaf(v2.y, t1.y, acc.y);
        acc.z = fmaf(v2.y, t1.z, acc.z);
        acc.w = fmaf(v2.y, t1.w, acc.w);
    }

    // trailing single edge
    if (e < end) {
        const float v = vals[e];
        const float4 t = emb4[cols[e] * (D_FEAT / 4) + fl];
        acc.x = fmaf(v, t.x, acc.x);
        acc.y = fmaf(v, t.y, acc.y);
        acc.z = fmaf(v, t.z, acc.z);
        acc.w = fmaf(v, t.w, acc.w);
    }

    // rows 2w and 2w+1 adjacent -> warp store is 512B contiguous.
    // Covers every row (empty rows store zeros) -> no memset needed.
    ((float4*)out)[row * (D_FEAT / 4) + fl] = acc;
}

extern "C" void kernel_launch(void* const* d_in, const int* in_sizes, int n_in,
                              void* d_out, int out_size)
{
    const int*   rows   = (const int*)d_in[0];
    const int*   cols   = (const int*)d_in[1];
    const float* vals   = (const float*)d_in[2];
    const float* embeds = (const float*)d_in[3];
    float*       out    = (float*)d_out;

    const int n_edges = in_sizes[0];
    const int n_nodes = out_size / D_FEAT;

    build_row_ptr<<<592, 256>>>(rows, n_edges, n_nodes);

    const int warps  = (n_nodes + 1) / 2;            // half-warp per row
    const int blocks = (warps * 32 + 255) / 256;
    spmm_csr<<<blocks, 256>>>(cols, vals, embeds, out, n_nodes);
}